// round 13
// baseline (speedup 1.0000x reference)
#include <cuda_runtime.h>
#include <cuda_bf16.h>

#define BATCH  32
#define T_     3749            // num frames per row
#define CROW   3750            // chunks per row
#define NCHUNK (BATCH*CROW)    // 120000
#define NBLK   148
#define TILE   811             // ceil(NCHUNK/NBLK)
#define SILF   18
#define MINSP  6
#define NWORDS 118             // ceil(3749/32)
#define MWSZ   132             // mask word storage (128 written + pad)
#define HB1    4096            // pass-1 bins (top 12 bits)
#define MAXG   256
#define KPAD   3776            // 118*32 padded keys

__device__ float    g_E[BATCH * T_];
__device__ int      g_hist[BATCH * HB1];  // zero at load; warp 0 restores zeros
__device__ int      g_nzero[BATCH];       // zero at load; warp 0 restores zeros
__device__ unsigned g_count;
__device__ unsigned g_epoch;

__device__ __forceinline__ void grid_barrier() {
    __syncthreads();
    if (threadIdx.x == 0) {
        unsigned e0 = *((volatile unsigned*)&g_epoch);
        __threadfence();
        unsigned a = atomicAdd(&g_count, 1u);
        if (a == NBLK - 1) {
            g_count = 0;
            __threadfence();
            atomicAdd(&g_epoch, 1u);
        } else {
            while (*((volatile unsigned*)&g_epoch) == e0) { }
        }
        __threadfence();
    }
    __syncthreads();
}

__device__ __forceinline__ int warp_incl_scan(int x, int lane) {
    #pragma unroll
    for (int o = 1; o < 32; o <<= 1) {
        int y = __shfl_up_sync(0xFFFFFFFFu, x, o);
        if (lane >= o) x += y;
    }
    return x;
}

__global__ __launch_bounds__(1024, 1)
void vad_fused_kernel(const float* __restrict__ W, float* __restrict__ out, int n_samples) {
    int tid = threadIdx.x, lane = tid & 31, wid = tid >> 5;

    __shared__ float    s_sum[TILE + 1];
    __shared__ unsigned ekey[KPAD];
    __shared__ int      hist_s[1024];
    __shared__ unsigned mword[MWSZ];
    __shared__ short    llist[MAXG];
    __shared__ short    vs_s[MAXG];
    __shared__ short    ve_s[MAXG];
    __shared__ int      G_sh;

    // ===== Phase 1: depth-4 pipelined chunk sums -> energies + hist + nzero =====
    int s0   = blockIdx.x * TILE;
    int len  = min(TILE, NCHUNK - s0);
    int nsum = min(len + 1, NCHUNK - s0);

    {
        float4 a0={0,0,0,0}, b0={0,0,0,0}, a1={0,0,0,0}, b1={0,0,0,0};
        float4 a2={0,0,0,0}, b2={0,0,0,0};
        int j = wid;
        if (j < nsum) {
            int c = s0 + j; int r = c / CROW, jj = c - r * CROW;
            const float4* p = (const float4*)(W + (size_t)r * n_samples) + (size_t)jj * 64;
            a0 = __ldcs(p + lane); b0 = __ldcs(p + lane + 32);
        }
        if (j + 32 < nsum) {
            int c = s0 + j + 32; int r = c / CROW, jj = c - r * CROW;
            const float4* p = (const float4*)(W + (size_t)r * n_samples) + (size_t)jj * 64;
            a1 = __ldcs(p + lane); b1 = __ldcs(p + lane + 32);
        }
        if (j + 64 < nsum) {
            int c = s0 + j + 64; int r = c / CROW, jj = c - r * CROW;
            const float4* p = (const float4*)(W + (size_t)r * n_samples) + (size_t)jj * 64;
            a2 = __ldcs(p + lane); b2 = __ldcs(p + lane + 32);
        }
        for (; j < nsum; j += 32) {
            float4 a3={0,0,0,0}, b3={0,0,0,0};
            if (j + 96 < nsum) {
                int c = s0 + j + 96; int r = c / CROW, jj = c - r * CROW;
                const float4* p = (const float4*)(W + (size_t)r * n_samples) + (size_t)jj * 64;
                a3 = __ldcs(p + lane); b3 = __ldcs(p + lane + 32);
            }
            float v = a0.x*a0.x + a0.y*a0.y + a0.z*a0.z + a0.w*a0.w
                    + b0.x*b0.x + b0.y*b0.y + b0.z*b0.z + b0.w*b0.w;
            #pragma unroll
            for (int o = 16; o; o >>= 1) v += __shfl_down_sync(0xFFFFFFFFu, v, o);
            if (lane == 0) s_sum[j] = v;
            a0 = a1; b0 = b1; a1 = a2; b1 = b2; a2 = a3; b2 = b3;
        }
    }
    __syncthreads();

    {
        int i = tid;
        bool ok = (i < len);
        int rowbin = -1;
        if (ok) {
            int t = s0 + i;
            int r = t / CROW;
            int tl = t - r * CROW;
            if (tl < CROW - 1) {
                float e = (s_sum[i] + s_sum[i + 1]) * (1.0f / 512.0f);
                g_E[r * T_ + tl] = e;
                if (e <= 0.0f) atomicAdd(&g_nzero[r], 1);
                rowbin = r * HB1 + (int)(__float_as_uint(e) >> 20);
            }
        }
        unsigned grp = __match_any_sync(0xFFFFFFFFu, rowbin);
        if (rowbin >= 0 && lane == __ffs(grp) - 1)
            atomicAdd(&g_hist[rowbin], __popc(grp));
    }

    grid_barrier();

    // ===== Phase 2: 2 block syncs. Stage A: keys->smem. Stage B: warp 0. Stage C: output =====
    if (blockIdx.x >= BATCH) return;
    int b = blockIdx.x;

    // ---- Stage A (block-wide) ----
    const float* Erow = g_E + b * T_;
    #pragma unroll
    for (int r = 0; r < 4; r++) {
        int i = r * 1024 + tid;
        if (i < KPAD) ekey[i] = (i < T_) ? __float_as_uint(Erow[i]) : 0u;
    }
    hist_s[tid] = 0;
    __syncthreads();

    // ---- Stage B (warp 0 only) ----
    if (wid == 0) {
        const unsigned F = 0xFFFFFFFFu;
        int nzero = g_nzero[b];
        if (lane == 0) g_nzero[b] = 0;

        int nz = T_ - nzero;
        float pos  = 0.2f * (float)(nz - 1);
        float flo  = floorf(pos);
        float frac = pos - flo;
        int ilo = min(max(nzero + (int)flo, 0), T_ - 1);
        int ihi = min(max(nzero + (int)ceilf(pos), 0), T_ - 1);

        // --- pass 1: rank-ilo bin among 4096 global bins (hierarchical warp scans) ---
        int* hrow = g_hist + b * HB1;
        int s1 = 0;
        {
            const int4* p4 = (const int4*)hrow + lane * 32;
            #pragma unroll 8
            for (int q = 0; q < 32; q++) { int4 v = p4[q]; s1 += v.x + v.y + v.z + v.w; }
        }
        int e1 = warp_incl_scan(s1, lane) - s1;
        unsigned sel = __ballot_sync(F, ilo >= e1 && ilo < e1 + s1);
        int L1 = __ffs(sel) - 1;
        int r1 = ilo - __shfl_sync(F, e1, L1);
        int4 v2 = ((const int4*)hrow)[L1 * 32 + lane];
        int s2 = v2.x + v2.y + v2.z + v2.w;
        int e2 = warp_incl_scan(s2, lane) - s2;
        sel = __ballot_sync(F, r1 >= e2 && r1 < e2 + s2);
        int L2 = __ffs(sel) - 1;
        int r2 = r1 - __shfl_sync(F, e2, L2);
        int bin1 = 0, rem = 0;
        if (lane == L2) {
            if      (r2 < v2.x)               { bin1 = 0; rem = r2; }
            else if (r2 < v2.x + v2.y)        { bin1 = 1; rem = r2 - v2.x; }
            else if (r2 < v2.x + v2.y + v2.z) { bin1 = 2; rem = r2 - v2.x - v2.y; }
            else                              { bin1 = 3; rem = r2 - v2.x - v2.y - v2.z; }
        }
        bin1 = __shfl_sync(F, bin1, L2);
        rem  = __shfl_sync(F, rem,  L2);
        unsigned prefix = (unsigned)(L1 * 128 + L2 * 4 + bin1) << 20;
        // restore zeros in g_hist row
        {
            int4 z = {0,0,0,0};
            int4* pw = (int4*)hrow + lane * 32;
            #pragma unroll 8
            for (int q = 0; q < 32; q++) pw[q] = z;
        }

        int k0 = lane * 118;
        int kn = max(0, min(118, T_ - k0));

        // --- pass 2: bits 19..10 ---
        for (int k = 0; k < kn; k++) {
            unsigned key = ekey[k0 + k];
            if ((key & 0xFFF00000u) == prefix) atomicAdd(&hist_s[(key >> 10) & 1023u], 1);
        }
        __syncwarp();
        {
            int ss = 0;
            const int4* hb = (const int4*)hist_s + lane * 8;
            #pragma unroll
            for (int q = 0; q < 8; q++) { int4 v = hb[q]; ss += v.x + v.y + v.z + v.w; }
            int ee = warp_incl_scan(ss, lane) - ss;
            sel = __ballot_sync(F, rem >= ee && rem < ee + ss);
            int La = __ffs(sel) - 1;
            int ra = rem - __shfl_sync(F, ee, La);
            int h1 = hist_s[La * 32 + lane];
            int eb = warp_incl_scan(h1, lane) - h1;
            sel = __ballot_sync(F, ra >= eb && ra < eb + h1);
            int Lb = __ffs(sel) - 1;
            rem = ra - __shfl_sync(F, eb, Lb);
            prefix |= (unsigned)(La * 32 + Lb) << 10;
            // zero hist
            int4 z = {0,0,0,0};
            int4* hw = (int4*)hist_s + lane * 8;
            #pragma unroll
            for (int q = 0; q < 8; q++) hw[q] = z;
        }
        __syncwarp();

        // --- pass 3: bits 9..0 ---
        for (int k = 0; k < kn; k++) {
            unsigned key = ekey[k0 + k];
            if ((key & 0xFFFFFC00u) == prefix) atomicAdd(&hist_s[key & 1023u], 1);
        }
        __syncwarp();
        unsigned vlob;
        {
            int ss = 0;
            const int4* hb = (const int4*)hist_s + lane * 8;
            #pragma unroll
            for (int q = 0; q < 8; q++) { int4 v = hb[q]; ss += v.x + v.y + v.z + v.w; }
            int ee = warp_incl_scan(ss, lane) - ss;
            sel = __ballot_sync(F, rem >= ee && rem < ee + ss);
            int La = __ffs(sel) - 1;
            int ra = rem - __shfl_sync(F, ee, La);
            int h1 = hist_s[La * 32 + lane];
            int eb = warp_incl_scan(h1, lane) - h1;
            sel = __ballot_sync(F, ra >= eb && ra < eb + h1);
            int Lb = __ffs(sel) - 1;
            vlob = prefix | (unsigned)(La * 32 + Lb);
        }

        // --- cle / mingt -> v_hi, thr ---
        int cle = 0;
        unsigned mg = 0xFFFFFFFFu;
        for (int k = 0; k < kn; k++) {
            unsigned key = ekey[k0 + k];
            if (key <= vlob) cle++;
            else mg = min(mg, key);
        }
        cle = __reduce_add_sync(F, cle);
        mg  = __reduce_min_sync(F, mg);
        float v_lo = __uint_as_float(vlob);
        float v_hi = (cle > ihi) ? v_lo : __uint_as_float(mg);
        float thr  = (nz > 0) ? (v_lo * (1.0f - frac) + v_hi * frac) : 0.01f;
        unsigned thrb = __float_as_uint(thr);   // thr > 0 always; uint cmp == float cmp

        // --- mask words (contiguous: lane*4+j), padding keys are 0 -> never set ---
        unsigned mwv[4];
        #pragma unroll
        for (int j = 0; j < 4; j++) {
            int w = (lane << 2) + j;
            unsigned m = 0;
            if (w < NWORDS) {
                int base = w << 5;
                #pragma unroll
                for (int k = 0; k < 32; k++)
                    m |= (ekey[base + k] > thrb ? 1u : 0u) << k;
            }
            mword[w] = m;
            mwv[j] = m;
        }
        if (lane < 4) mword[128 + lane] = 0u;
        __syncwarp();

        // --- flags via 64-bit window-OR; ordinal pairing; intervals ---
        unsigned swv[4], lwv[4];
        int scnt = 0, lcnt = 0;
        #pragma unroll
        for (int j = 0; j < 4; j++) {
            int w = (lane << 2) + j;
            unsigned sw = 0, lw = 0;
            if (w < NWORDS) {
                unsigned mp = w ? mword[w - 1] : 0u;
                unsigned mc = mwv[j];
                unsigned mn = mword[w + 1];
                unsigned long long X = ((unsigned long long)mc << 32) | mp;
                unsigned long long z = (X << 1) | (X << 2);
                z |= z << 2; z |= z << 4; z |= z << 8;
                z |= (X << 17) | (X << 18);
                sw = mc & ~(unsigned)(z >> 32);
                unsigned long long Y = ((unsigned long long)mn << 32) | mc;
                unsigned long long q = (Y >> 1) | (Y >> 2);
                q |= q >> 2; q |= q >> 4; q |= q >> 8;
                q |= (Y >> 17) | (Y >> 18);
                lw = mc & ~(unsigned)q;
            }
            swv[j] = sw; lwv[j] = lw;
            scnt += __popc(sw); lcnt += __popc(lw);
        }
        int packed = scnt | (lcnt << 16);
        int x = warp_incl_scan(packed, lane);
        int excl = x - packed;
        if (lane == 31) G_sh = (x >> 16);
        {
            int rank = excl >> 16;
            #pragma unroll
            for (int j = 0; j < 4; j++) {
                unsigned lw = lwv[j];
                int basep = ((lane << 2) + j) << 5;
                while (lw) {
                    int k = __ffs(lw) - 1; lw &= lw - 1u;
                    llist[rank++] = (short)(basep + k);
                }
            }
        }
        __syncwarp();
        {
            int rank = excl & 0xFFFF;
            #pragma unroll
            for (int j = 0; j < 4; j++) {
                unsigned sw = swv[j];
                int basep = ((lane << 2) + j) << 5;
                while (sw) {
                    int k = __ffs(sw) - 1; sw &= sw - 1u;
                    int t = basep + k;
                    int l = llist[rank];
                    bool closed = (l + SILF <= T_ - 1);
                    int end = closed ? l : T_;   // closed end excludes the last 1 (reference)
                    bool valid = (end - t >= MINSP);
                    vs_s[rank] = (short)t;
                    ve_s[rank] = (short)(valid ? end : t);  // empty if invalid
                    rank++;
                }
            }
        }
    }
    __syncthreads();

    // ---- Stage C: output (block-wide, binary search; G usually 1) ----
    int G = G_sh;
    float* orow = out + (size_t)b * T_;
    #pragma unroll
    for (int r = 0; r < 4; r++) {
        int p = r * 1024 + tid;
        if (p < T_) {
            float o = 0.0f;
            if (G > 0 && (int)vs_s[0] <= p) {
                int lo = 0, hi = G - 1;
                while (lo < hi) {
                    int mid = (lo + hi + 1) >> 1;
                    if ((int)vs_s[mid] <= p) lo = mid; else hi = mid - 1;
                }
                if (p < (int)ve_s[lo]) o = 1.0f;
            }
            orow[p] = o;
        }
    }
}

extern "C" void kernel_launch(void* const* d_in, const int* in_sizes, int n_in,
                              void* d_out, int out_size) {
    const float* W = (const float*)d_in[0];
    int n_samples = in_sizes[0] / BATCH;   // 960000
    vad_fused_kernel<<<NBLK, 1024>>>(W, (float*)d_out, n_samples);
}

// round 14
// speedup vs baseline: 1.5938x; 1.5938x over previous
#include <cuda_runtime.h>
#include <cuda_bf16.h>

#define BATCH  32
#define T_     3749            // num frames per row
#define CROW   3750            // chunks per row
#define NCHUNK (BATCH*CROW)    // 120000
#define NBLK   148
#define TILE   811             // ceil(NCHUNK/NBLK)
#define SILF   18
#define MINSP  6
#define WN32   120             // mask words storage (padded)
#define NWORDS 118             // ceil(3749/32)
#define HB1    4096            // pass-1 bins (top 12 bits)
#define MAXG   256

__device__ float    g_E[BATCH * T_];
__device__ int      g_hist[BATCH * HB1];  // zero at load; phase 2 restores zeros
__device__ int      g_nzero[BATCH];       // zero at load; phase 2 restores zeros
__device__ unsigned g_count;
__device__ unsigned g_epoch;

__device__ __forceinline__ void grid_barrier() {
    __syncthreads();
    if (threadIdx.x == 0) {
        unsigned e0 = *((volatile unsigned*)&g_epoch);
        __threadfence();
        unsigned a = atomicAdd(&g_count, 1u);
        if (a == NBLK - 1) {
            g_count = 0;
            __threadfence();
            atomicAdd(&g_epoch, 1u);
        } else {
            while (*((volatile unsigned*)&g_epoch) == e0) { }
        }
        __threadfence();
    }
    __syncthreads();
}

__device__ __forceinline__ int warp_incl_scan(int x, int lane) {
    #pragma unroll
    for (int o = 1; o < 32; o <<= 1) {
        int y = __shfl_up_sync(0xFFFFFFFFu, x, o);
        if (lane >= o) x += y;
    }
    return x;
}
// exclusive block scan, 2 syncs. SAFE ONLY because every call site is followed
// by a __syncthreads() before the next call writes warp_sums again.
__device__ __forceinline__ int block_excl_scan(int v, int lane, int wid, int* ws) {
    int x = warp_incl_scan(v, lane);
    if (lane == 31) ws[wid] = x;
    __syncthreads();
    if (wid == 0) {
        int t = ws[lane];
        int xx = warp_incl_scan(t, lane);
        ws[lane] = xx - t;
    }
    __syncthreads();
    return ws[wid] + x - v;
}

__global__ __launch_bounds__(1024, 1)
void vad_fused_kernel(const float* __restrict__ W, float* __restrict__ out, int n_samples) {
    int tid = threadIdx.x, lane = tid & 31, wid = tid >> 5;

    __shared__ float    s_sum[TILE + 1];
    __shared__ int      hist_s[1024];
    __shared__ unsigned mword[WN32], lword[WN32], sword[WN32];
    __shared__ int      woff[WN32];
    __shared__ short    llist[MAXG];
    __shared__ short    vs_s[MAXG];
    __shared__ short    ve_s[MAXG];
    __shared__ int      warp_sums[32];
    __shared__ unsigned mg_w[32];
    __shared__ int      r_sh, tot_sh;
    __shared__ unsigned prefix_sh, phi_sh;
    __shared__ int      G_sh;

    // ===== Phase 1: depth-4 pipelined chunk sums -> energies + hist + nzero =====
    int s0   = blockIdx.x * TILE;
    int len  = min(TILE, NCHUNK - s0);
    int nsum = min(len + 1, NCHUNK - s0);

    {
        float4 a0={0,0,0,0}, b0={0,0,0,0}, a1={0,0,0,0}, b1={0,0,0,0};
        float4 a2={0,0,0,0}, b2={0,0,0,0};
        int j = wid;
        if (j < nsum) {
            int c = s0 + j; int r = c / CROW, jj = c - r * CROW;
            const float4* p = (const float4*)(W + (size_t)r * n_samples) + (size_t)jj * 64;
            a0 = __ldcs(p + lane); b0 = __ldcs(p + lane + 32);
        }
        if (j + 32 < nsum) {
            int c = s0 + j + 32; int r = c / CROW, jj = c - r * CROW;
            const float4* p = (const float4*)(W + (size_t)r * n_samples) + (size_t)jj * 64;
            a1 = __ldcs(p + lane); b1 = __ldcs(p + lane + 32);
        }
        if (j + 64 < nsum) {
            int c = s0 + j + 64; int r = c / CROW, jj = c - r * CROW;
            const float4* p = (const float4*)(W + (size_t)r * n_samples) + (size_t)jj * 64;
            a2 = __ldcs(p + lane); b2 = __ldcs(p + lane + 32);
        }
        for (; j < nsum; j += 32) {
            float4 a3={0,0,0,0}, b3={0,0,0,0};
            if (j + 96 < nsum) {
                int c = s0 + j + 96; int r = c / CROW, jj = c - r * CROW;
                const float4* p = (const float4*)(W + (size_t)r * n_samples) + (size_t)jj * 64;
                a3 = __ldcs(p + lane); b3 = __ldcs(p + lane + 32);
            }
            float v = a0.x*a0.x + a0.y*a0.y + a0.z*a0.z + a0.w*a0.w
                    + b0.x*b0.x + b0.y*b0.y + b0.z*b0.z + b0.w*b0.w;
            #pragma unroll
            for (int o = 16; o; o >>= 1) v += __shfl_down_sync(0xFFFFFFFFu, v, o);
            if (lane == 0) s_sum[j] = v;
            a0 = a1; b0 = b1; a1 = a2; b1 = b2; a2 = a3; b2 = b3;
        }
    }
    __syncthreads();

    {
        int i = tid;
        bool ok = (i < len);
        int rowbin = -1;
        if (ok) {
            int t = s0 + i;
            int r = t / CROW;
            int tl = t - r * CROW;
            if (tl < CROW - 1) {
                float e = (s_sum[i] + s_sum[i + 1]) * (1.0f / 512.0f);
                g_E[r * T_ + tl] = e;
                if (e <= 0.0f) atomicAdd(&g_nzero[r], 1);
                rowbin = r * HB1 + (int)(__float_as_uint(e) >> 20);
            }
        }
        unsigned grp = __match_any_sync(0xFFFFFFFFu, rowbin);
        if (rowbin >= 0 && lane == __ffs(grp) - 1)
            atomicAdd(&g_hist[rowbin], __popc(grp));
    }

    grid_barrier();

    // ===== Phase 2: per-row VAD, register-resident keys =====
    if (blockIdx.x >= BATCH) return;
    int b = blockIdx.x;

    hist_s[tid] = 0;

    unsigned key[4]; bool kval[4];
    const float* Erow = g_E + b * T_;
    #pragma unroll
    for (int r = 0; r < 4; r++) {
        int i = r * 1024 + tid;
        kval[r] = (i < T_);
        key[r] = kval[r] ? __float_as_uint(Erow[i]) : 0u;
    }
    int nzero = g_nzero[b];
    int4 hv = ((const int4*)(g_hist + b * HB1))[tid];
    ((int4*)(g_hist + b * HB1))[tid] = make_int4(0, 0, 0, 0);
    __syncthreads();
    if (tid == 0) g_nzero[b] = 0;

    int nz = T_ - nzero;
    float pos  = 0.2f * (float)(nz - 1);
    float flo  = floorf(pos);
    float frac = pos - flo;
    int ilo = min(max(nzero + (int)flo, 0), T_ - 1);
    int ihi = min(max(nzero + (int)ceilf(pos), 0), T_ - 1);
    int dhi = ihi - ilo;   // 0 or 1

    // ---- pass 1: top-12-bit bin from precomputed hist ----
    int base4 = tid << 2;
    int tsum = hv.x + hv.y + hv.z + hv.w;
    int texcl = block_excl_scan(tsum, lane, wid, warp_sums);
    {
        int cum = texcl;
        if (ilo >= cum && ilo < cum + hv.x) { r_sh = ilo - cum; prefix_sh = (unsigned)(base4 + 0) << 20; }
        cum += hv.x;
        if (ilo >= cum && ilo < cum + hv.y) { r_sh = ilo - cum; prefix_sh = (unsigned)(base4 + 1) << 20; }
        cum += hv.y;
        if (ilo >= cum && ilo < cum + hv.z) { r_sh = ilo - cum; prefix_sh = (unsigned)(base4 + 2) << 20; }
        cum += hv.z;
        if (ilo >= cum && ilo < cum + hv.w) { r_sh = ilo - cum; prefix_sh = (unsigned)(base4 + 3) << 20; }
    }
    __syncthreads();
    unsigned prefix = prefix_sh;

    // ---- pass 2: bits 19..10 (plain atomics; few participants, spread bins) ----
    #pragma unroll
    for (int r = 0; r < 4; r++) {
        if (kval[r] && ((key[r] & 0xFFF00000u) == prefix))
            atomicAdd(&hist_s[(key[r] >> 10) & 1023u], 1);
    }
    __syncthreads();
    {
        int h = hist_s[tid]; hist_s[tid] = 0;
        int rr = r_sh;
        int excl = block_excl_scan(h, lane, wid, warp_sums);
        if (rr >= excl && rr < excl + h) {
            r_sh = rr - excl;
            prefix_sh = prefix | ((unsigned)tid << 10);
            tot_sh = h;     // count of keys matching the 22-bit prefix
        }
    }
    __syncthreads();
    prefix = prefix_sh;

    // ---- pass 3: bits 9..0 (plain atomics), dual-rank selection ----
    #pragma unroll
    for (int r = 0; r < 4; r++) {
        if (kval[r] && ((key[r] & 0xFFFFFC00u) == prefix))
            atomicAdd(&hist_s[key[r] & 1023u], 1);
    }
    __syncthreads();
    int tot = tot_sh;
    int rl  = r_sh;
    int rh  = rl + dhi;
    bool hi_in = (rh < tot);    // uniform across block
    {
        int h = hist_s[tid];
        int excl = block_excl_scan(h, lane, wid, warp_sums);
        if (rl >= excl && rl < excl + h) prefix_sh = prefix | (unsigned)tid;
        if (hi_in && rh >= excl && rh < excl + h) phi_sh = prefix | (unsigned)tid;
    }
    __syncthreads();
    float v_lo = __uint_as_float(prefix_sh);
    float v_hi;
    if (hi_in) {
        v_hi = __uint_as_float(phi_sh);
    } else {
        // rare: rank ihi lies above the 22-bit region -> min key above region
        unsigned mg = 0xFFFFFFFFu;
        #pragma unroll
        for (int r = 0; r < 4; r++) {
            if (kval[r] && ((key[r] & 0xFFFFFC00u) > prefix)) mg = min(mg, key[r]);
        }
        #pragma unroll
        for (int o = 16; o; o >>= 1) mg = min(mg, __shfl_down_sync(0xFFFFFFFFu, mg, o));
        if (lane == 0) mg_w[wid] = mg;
        __syncthreads();
        if (wid == 0) {
            unsigned m = mg_w[lane];
            #pragma unroll
            for (int o = 16; o; o >>= 1) m = min(m, __shfl_down_sync(0xFFFFFFFFu, m, o));
            if (lane == 0) mg_w[0] = m;
        }
        __syncthreads();
        v_hi = __uint_as_float(mg_w[0]);
    }
    float thr = (nz > 0) ? (v_lo * (1.0f - frac) + v_hi * frac) : 0.01f;

    // ---- mask ballot from register keys ----
    #pragma unroll
    for (int r = 0; r < 4; r++) {
        int i = r * 1024 + tid;
        bool pred = kval[r] && (__uint_as_float(key[r]) > thr);
        unsigned w = __ballot_sync(0xFFFFFFFFu, pred);
        if (lane == 0 && (i >> 5) < WN32) mword[i >> 5] = w;
    }
    __syncthreads();

    // ---- word-parallel start/last flags via 64-bit window-OR ----
    int cnt = 0;
    if (tid < NWORDS) {
        unsigned mp = tid ? mword[tid - 1] : 0u;
        unsigned mc = mword[tid];
        unsigned mn = mword[tid + 1];   // words 118/119 are zero
        unsigned long long X = ((unsigned long long)mc << 32) | mp;
        unsigned long long z = (X << 1) | (X << 2);
        z |= z << 2; z |= z << 4; z |= z << 8;
        z |= (X << 17) | (X << 18);
        unsigned sw = mc & ~(unsigned)(z >> 32);
        unsigned long long Y = ((unsigned long long)mn << 32) | mc;
        unsigned long long q = (Y >> 1) | (Y >> 2);
        q |= q >> 2; q |= q >> 4; q |= q >> 8;
        q |= (Y >> 17) | (Y >> 18);
        unsigned lw = mc & ~(unsigned)q;
        sword[tid] = sw; lword[tid] = lw;
        cnt = __popc(sw) | (__popc(lw) << 16);
    }
    {
        int excl = block_excl_scan(cnt, lane, wid, warp_sums);
        if (tid < NWORDS) woff[tid] = excl;
        if (tid == NWORDS - 1) G_sh = (excl + cnt) & 0xFFFF;
    }
    __syncthreads();

    // lasts write positions by ordinal
    if (tid < NWORDS) {
        unsigned lw = lword[tid];
        int rank = woff[tid] >> 16;
        int basep = tid << 5;
        while (lw) {
            int k = __ffs(lw) - 1; lw &= lw - 1u;
            llist[rank++] = (short)(basep + k);
        }
    }
    __syncthreads();

    // starts pair with same-ordinal last; emit compact sorted intervals
    if (tid < NWORDS) {
        unsigned sw = sword[tid];
        int rank = woff[tid] & 0xFFFF;
        int basep = tid << 5;
        while (sw) {
            int k = __ffs(sw) - 1; sw &= sw - 1u;
            int t = basep + k;
            int l = llist[rank];
            bool closed = (l + SILF <= T_ - 1);
            int end = closed ? l : T_;      // closed end excludes the last 1 (reference)
            bool valid = (end - t >= MINSP);
            vs_s[rank] = (short)t;
            ve_s[rank] = (short)(valid ? end : t);   // empty interval if invalid
            rank++;
        }
    }
    __syncthreads();

    // ---- output: covered iff inside interval (binary search, G usually 1) ----
    int G = G_sh;
    float* orow = out + (size_t)b * T_;
    #pragma unroll
    for (int r = 0; r < 4; r++) {
        int p = r * 1024 + tid;
        if (p < T_) {
            float o = 0.0f;
            if (G > 0 && (int)vs_s[0] <= p) {
                int lo = 0, hi = G - 1;
                while (lo < hi) {
                    int mid = (lo + hi + 1) >> 1;
                    if ((int)vs_s[mid] <= p) lo = mid; else hi = mid - 1;
                }
                if (p < (int)ve_s[lo]) o = 1.0f;
            }
            orow[p] = o;
        }
    }
}

extern "C" void kernel_launch(void* const* d_in, const int* in_sizes, int n_in,
                              void* d_out, int out_size) {
    const float* W = (const float*)d_in[0];
    int n_samples = in_sizes[0] / BATCH;   // 960000
    vad_fused_kernel<<<NBLK, 1024>>>(W, (float*)d_out, n_samples);
}

// round 15
// speedup vs baseline: 1.6864x; 1.0581x over previous
#include <cuda_runtime.h>
#include <cuda_bf16.h>

#define BATCH  32
#define T_     3749            // num frames per row
#define CROW   3750            // chunks per row
#define NCHUNK (BATCH*CROW)    // 120000
#define NBLK   148
#define TILE   811             // ceil(NCHUNK/NBLK)
#define SILF   18
#define MINSP  6
#define WN32   120             // mask words storage (padded)
#define NWORDS 118             // ceil(3749/32)
#define HB1    4096            // pass-1 bins (top 12 bits)
#define MAXG   256

__device__ float    g_E[BATCH * T_];
__device__ int      g_hist[BATCH * HB1];  // zero at load; phase 2 restores zeros
__device__ int      g_nzero[BATCH];       // zero at load; phase 2 restores zeros
__device__ unsigned g_count;
__device__ unsigned g_epoch;

__device__ __forceinline__ void grid_barrier() {
    __syncthreads();
    if (threadIdx.x == 0) {
        unsigned e0 = *((volatile unsigned*)&g_epoch);
        __threadfence();
        unsigned a = atomicAdd(&g_count, 1u);
        if (a == NBLK - 1) {
            g_count = 0;
            __threadfence();
            atomicAdd(&g_epoch, 1u);
        } else {
            while (*((volatile unsigned*)&g_epoch) == e0) { }
        }
        __threadfence();
    }
    __syncthreads();
}

__device__ __forceinline__ int warp_incl_scan(int x, int lane) {
    #pragma unroll
    for (int o = 1; o < 32; o <<= 1) {
        int y = __shfl_up_sync(0xFFFFFFFFu, x, o);
        if (lane >= o) x += y;
    }
    return x;
}

__global__ __launch_bounds__(1024, 1)
void vad_fused_kernel(const float* __restrict__ W, float* __restrict__ out, int n_samples) {
    int tid = threadIdx.x, lane = tid & 31, wid = tid >> 5;

    __shared__ float    s_sum[TILE + 1];
    __shared__ int      hist_s[1024];
    __shared__ unsigned mword[WN32], lword[WN32], sword[WN32];
    __shared__ short    llist[MAXG];
    __shared__ short    vs_s[MAXG];
    __shared__ short    ve_s[MAXG];
    __shared__ int      warp_sums[32];
    __shared__ unsigned mg_w[32];
    __shared__ int      r_sh, tot_sh;
    __shared__ unsigned prefix_sh, phi_sh;
    __shared__ int      G_sh;

    // ===== Phase 1: depth-4 pipelined chunk sums -> energies + hist + nzero =====
    int s0   = blockIdx.x * TILE;
    int len  = min(TILE, NCHUNK - s0);
    int nsum = min(len + 1, NCHUNK - s0);

    {
        float4 a0={0,0,0,0}, b0={0,0,0,0}, a1={0,0,0,0}, b1={0,0,0,0};
        float4 a2={0,0,0,0}, b2={0,0,0,0};
        int j = wid;
        if (j < nsum) {
            int c = s0 + j; int r = c / CROW, jj = c - r * CROW;
            const float4* p = (const float4*)(W + (size_t)r * n_samples) + (size_t)jj * 64;
            a0 = __ldcs(p + lane); b0 = __ldcs(p + lane + 32);
        }
        if (j + 32 < nsum) {
            int c = s0 + j + 32; int r = c / CROW, jj = c - r * CROW;
            const float4* p = (const float4*)(W + (size_t)r * n_samples) + (size_t)jj * 64;
            a1 = __ldcs(p + lane); b1 = __ldcs(p + lane + 32);
        }
        if (j + 64 < nsum) {
            int c = s0 + j + 64; int r = c / CROW, jj = c - r * CROW;
            const float4* p = (const float4*)(W + (size_t)r * n_samples) + (size_t)jj * 64;
            a2 = __ldcs(p + lane); b2 = __ldcs(p + lane + 32);
        }
        for (; j < nsum; j += 32) {
            float4 a3={0,0,0,0}, b3={0,0,0,0};
            if (j + 96 < nsum) {
                int c = s0 + j + 96; int r = c / CROW, jj = c - r * CROW;
                const float4* p = (const float4*)(W + (size_t)r * n_samples) + (size_t)jj * 64;
                a3 = __ldcs(p + lane); b3 = __ldcs(p + lane + 32);
            }
            float v = a0.x*a0.x + a0.y*a0.y + a0.z*a0.z + a0.w*a0.w
                    + b0.x*b0.x + b0.y*b0.y + b0.z*b0.z + b0.w*b0.w;
            #pragma unroll
            for (int o = 16; o; o >>= 1) v += __shfl_down_sync(0xFFFFFFFFu, v, o);
            if (lane == 0) s_sum[j] = v;
            a0 = a1; b0 = b1; a1 = a2; b1 = b2; a2 = a3; b2 = b3;
        }
    }
    __syncthreads();

    {
        int i = tid;
        bool ok = (i < len);
        int rowbin = -1;
        if (ok) {
            int t = s0 + i;
            int r = t / CROW;
            int tl = t - r * CROW;
            if (tl < CROW - 1) {
                float e = (s_sum[i] + s_sum[i + 1]) * (1.0f / 512.0f);
                g_E[r * T_ + tl] = e;
                if (e <= 0.0f) atomicAdd(&g_nzero[r], 1);
                rowbin = r * HB1 + (int)(__float_as_uint(e) >> 20);
            }
        }
        unsigned grp = __match_any_sync(0xFFFFFFFFu, rowbin);
        if (rowbin >= 0 && lane == __ffs(grp) - 1)
            atomicAdd(&g_hist[rowbin], __popc(grp));
    }

    grid_barrier();

    // ===== Phase 2: per-row VAD (12 block syncs total) =====
    if (blockIdx.x >= BATCH) return;
    int b = blockIdx.x;

    // ---- fused stage A + pass-1 scan front ----
    hist_s[tid] = 0;
    unsigned key[4]; bool kval[4];
    const float* Erow = g_E + b * T_;
    #pragma unroll
    for (int r = 0; r < 4; r++) {
        int i = r * 1024 + tid;
        kval[r] = (i < T_);
        key[r] = kval[r] ? __float_as_uint(Erow[i]) : 0u;
    }
    int nzero = g_nzero[b];
    int4 hv = ((const int4*)(g_hist + b * HB1))[tid];
    ((int4*)(g_hist + b * HB1))[tid] = make_int4(0, 0, 0, 0);

    int nz = T_ - nzero;
    float pos  = 0.2f * (float)(nz - 1);
    float flo  = floorf(pos);
    float frac = pos - flo;
    int ilo = min(max(nzero + (int)flo, 0), T_ - 1);
    int ihi = min(max(nzero + (int)ceilf(pos), 0), T_ - 1);
    int dhi = ihi - ilo;   // 0 or 1

    int base4 = tid << 2;
    int tsum = hv.x + hv.y + hv.z + hv.w;
    int x1 = warp_incl_scan(tsum, lane);
    if (lane == 31) warp_sums[wid] = x1;
    __syncthreads();                                                   // S1
    {
        int off = __reduce_add_sync(0xFFFFFFFFu, (lane < wid) ? warp_sums[lane] : 0);
        int cum = off + x1 - tsum;
        if (ilo >= cum && ilo < cum + hv.x) { r_sh = ilo - cum; prefix_sh = (unsigned)(base4 + 0) << 20; }
        cum += hv.x;
        if (ilo >= cum && ilo < cum + hv.y) { r_sh = ilo - cum; prefix_sh = (unsigned)(base4 + 1) << 20; }
        cum += hv.y;
        if (ilo >= cum && ilo < cum + hv.z) { r_sh = ilo - cum; prefix_sh = (unsigned)(base4 + 2) << 20; }
        cum += hv.z;
        if (ilo >= cum && ilo < cum + hv.w) { r_sh = ilo - cum; prefix_sh = (unsigned)(base4 + 3) << 20; }
    }
    if (tid == 0) g_nzero[b] = 0;
    __syncthreads();                                                   // S2
    unsigned prefix = prefix_sh;

    // ---- pass 2: bits 19..10 ----
    #pragma unroll
    for (int r = 0; r < 4; r++) {
        if (kval[r] && ((key[r] & 0xFFF00000u) == prefix))
            atomicAdd(&hist_s[(key[r] >> 10) & 1023u], 1);
    }
    __syncthreads();                                                   // S3
    {
        int h = hist_s[tid]; hist_s[tid] = 0;
        int rr = r_sh;
        int x = warp_incl_scan(h, lane);
        if (lane == 31) warp_sums[wid] = x;
        __syncthreads();                                               // S4
        int off = __reduce_add_sync(0xFFFFFFFFu, (lane < wid) ? warp_sums[lane] : 0);
        int excl = off + x - h;
        if (rr >= excl && rr < excl + h) {
            r_sh = rr - excl;
            prefix_sh = prefix | ((unsigned)tid << 10);
            tot_sh = h;
        }
    }
    __syncthreads();                                                   // S5
    prefix = prefix_sh;

    // ---- pass 3: bits 9..0, dual-rank selection ----
    #pragma unroll
    for (int r = 0; r < 4; r++) {
        if (kval[r] && ((key[r] & 0xFFFFFC00u) == prefix))
            atomicAdd(&hist_s[key[r] & 1023u], 1);
    }
    __syncthreads();                                                   // S6
    int tot = tot_sh;
    int rl  = r_sh;
    int rh  = rl + dhi;
    bool hi_in = (rh < tot);    // uniform across block
    {
        int h = hist_s[tid];
        int x = warp_incl_scan(h, lane);
        if (lane == 31) warp_sums[wid] = x;
        __syncthreads();                                               // S7
        int off = __reduce_add_sync(0xFFFFFFFFu, (lane < wid) ? warp_sums[lane] : 0);
        int excl = off + x - h;
        if (rl >= excl && rl < excl + h) prefix_sh = prefix | (unsigned)tid;
        if (hi_in && rh >= excl && rh < excl + h) phi_sh = prefix | (unsigned)tid;
    }
    __syncthreads();                                                   // S8
    float v_lo = __uint_as_float(prefix_sh);
    float v_hi;
    if (hi_in) {
        v_hi = __uint_as_float(phi_sh);
    } else {
        // rare: rank ihi above the 22-bit region -> min key above region
        unsigned mg = 0xFFFFFFFFu;
        #pragma unroll
        for (int r = 0; r < 4; r++) {
            if (kval[r] && ((key[r] & 0xFFFFFC00u) > prefix)) mg = min(mg, key[r]);
        }
        #pragma unroll
        for (int o = 16; o; o >>= 1) mg = min(mg, __shfl_down_sync(0xFFFFFFFFu, mg, o));
        if (lane == 0) mg_w[wid] = mg;
        __syncthreads();
        if (wid == 0) {
            unsigned m = mg_w[lane];
            #pragma unroll
            for (int o = 16; o; o >>= 1) m = min(m, __shfl_down_sync(0xFFFFFFFFu, m, o));
            if (lane == 0) mg_w[0] = m;
        }
        __syncthreads();
        v_hi = __uint_as_float(mg_w[0]);
    }
    float thr = (nz > 0) ? (v_lo * (1.0f - frac) + v_hi * frac) : 0.01f;

    // ---- mask ballot from register keys ----
    #pragma unroll
    for (int r = 0; r < 4; r++) {
        int i = r * 1024 + tid;
        bool pred = kval[r] && (__uint_as_float(key[r]) > thr);
        unsigned w = __ballot_sync(0xFFFFFFFFu, pred);
        if (lane == 0 && (i >> 5) < WN32) mword[i >> 5] = w;
    }
    __syncthreads();                                                   // S9

    // ---- flags + ordinal scan + llist (one stage) ----
    unsigned swv = 0, lwv = 0;
    int cnt = 0;
    if (tid < NWORDS) {
        unsigned mp = tid ? mword[tid - 1] : 0u;
        unsigned mc = mword[tid];
        unsigned mn = mword[tid + 1];   // words 118/119 are zero
        unsigned long long X = ((unsigned long long)mc << 32) | mp;
        unsigned long long z = (X << 1) | (X << 2);
        z |= z << 2; z |= z << 4; z |= z << 8;
        z |= (X << 17) | (X << 18);
        swv = mc & ~(unsigned)(z >> 32);
        unsigned long long Y = ((unsigned long long)mn << 32) | mc;
        unsigned long long q = (Y >> 1) | (Y >> 2);
        q |= q >> 2; q |= q >> 4; q |= q >> 8;
        q |= (Y >> 17) | (Y >> 18);
        lwv = mc & ~(unsigned)q;
        sword[tid] = swv; lword[tid] = lwv;
        cnt = __popc(swv) | (__popc(lwv) << 16);
    }
    int excl_fl;
    {
        int x = warp_incl_scan(cnt, lane);
        if (lane == 31) warp_sums[wid] = x;
        __syncthreads();                                               // S10
        int off = __reduce_add_sync(0xFFFFFFFFu, (lane < wid) ? warp_sums[lane] : 0);
        excl_fl = off + x - cnt;
        if (tid == NWORDS - 1) G_sh = (excl_fl + cnt) & 0xFFFF;
        // lasts write positions by ordinal (same stage; own data only)
        if (tid < NWORDS) {
            unsigned lw = lwv;
            int rank = excl_fl >> 16;
            int basep = tid << 5;
            while (lw) {
                int k = __ffs(lw) - 1; lw &= lw - 1u;
                llist[rank++] = (short)(basep + k);
            }
        }
    }
    __syncthreads();                                                   // S11

    // starts pair with same-ordinal last; emit compact sorted intervals
    if (tid < NWORDS) {
        unsigned sw = swv;
        int rank = excl_fl & 0xFFFF;
        int basep = tid << 5;
        while (sw) {
            int k = __ffs(sw) - 1; sw &= sw - 1u;
            int t = basep + k;
            int l = llist[rank];
            bool closed = (l + SILF <= T_ - 1);
            int end = closed ? l : T_;      // closed end excludes the last 1 (reference)
            bool valid = (end - t >= MINSP);
            vs_s[rank] = (short)t;
            ve_s[rank] = (short)(valid ? end : t);   // empty interval if invalid
            rank++;
        }
    }
    __syncthreads();                                                   // S12

    // ---- output: covered iff inside interval (binary search, G usually 1) ----
    int G = G_sh;
    float* orow = out + (size_t)b * T_;
    #pragma unroll
    for (int r = 0; r < 4; r++) {
        int p = r * 1024 + tid;
        if (p < T_) {
            float o = 0.0f;
            if (G > 0 && (int)vs_s[0] <= p) {
                int lo = 0, hi = G - 1;
                while (lo < hi) {
                    int mid = (lo + hi + 1) >> 1;
                    if ((int)vs_s[mid] <= p) lo = mid; else hi = mid - 1;
                }
                if (p < (int)ve_s[lo]) o = 1.0f;
            }
            orow[p] = o;
        }
    }
}

extern "C" void kernel_launch(void* const* d_in, const int* in_sizes, int n_in,
                              void* d_out, int out_size) {
    const float* W = (const float*)d_in[0];
    int n_samples = in_sizes[0] / BATCH;   // 960000
    vad_fused_kernel<<<NBLK, 1024>>>(W, (float*)d_out, n_samples);
}